// round 3
// baseline (speedup 1.0000x reference)
#include <cuda_runtime.h>
#include <math.h>

#define N_NODES 100000
#define N_EDGES 600000
#define F1 128
#define F2 64

// ---------------- scratch (static device globals; no allocation) ----------------
__device__ __align__(16) float g_deg [N_NODES];
__device__ __align__(16) float g_dinv[N_NODES];
__device__ __align__(16) float g_tmp1[N_NODES * F1];  // x @ W1
__device__ __align__(16) float g_h1  [N_NODES * F1];  // aggregated layer-1 out (pre-ReLU)
__device__ __align__(16) float g_tmp2[N_NODES * F2];  // relu(h1) @ W2

// ---------------- degree / norm ----------------
__global__ void k_init_deg() {
    int i = blockIdx.x * blockDim.x + threadIdx.x;
    if (i < N_NODES) g_deg[i] = 1.0f;   // self loop
}

__global__ void k_deg_edges(const int* __restrict__ dst) {
    int e = blockIdx.x * blockDim.x + threadIdx.x;
    if (e < N_EDGES) {
        int d = dst[e];
        if (d >= 0 && d < N_NODES) atomicAdd(&g_deg[d], 1.0f);
    }
}

__global__ void k_dinv() {
    int i = blockIdx.x * blockDim.x + threadIdx.x;
    if (i < N_NODES) g_dinv[i] = rsqrtf(g_deg[i]);   // deg >= 1 always
}

// ---------------- SGEMM: C[M x BN] = op(A)[M x 128] * B[128 x BN] ----------------
// BM=128, BK=8, 8x8 thread tile.
// A_GLOBAL: 0 -> A param, 1 -> g_h1 (with ReLU on load)
// C_SEL:    1 -> g_tmp1, 2 -> g_tmp2
template <int BN, int A_GLOBAL, int C_SEL>
__global__ void __launch_bounds__(16 * (BN / 8))
k_gemm(const float* __restrict__ Ap, const float* __restrict__ B) {
    constexpr int BM = 128;
    constexpr int BK = 8;
    constexpr int K  = 128;
    constexpr int TX = BN / 8;        // threads along n
    constexpr int NT = 16 * TX;       // total threads
    __shared__ float As[BK][BM];
    __shared__ float Bs[BK][BN];

    const float* A = A_GLOBAL ? (const float*)g_h1 : Ap;
    float* C = (C_SEL == 1) ? (float*)g_tmp1 : (float*)g_tmp2;

    const int tid = threadIdx.x;
    const int tx  = tid % TX;
    const int ty  = tid / TX;         // [0,16)
    const int row0 = blockIdx.x * BM;

    float acc[8][8];
#pragma unroll
    for (int i = 0; i < 8; i++)
#pragma unroll
        for (int j = 0; j < 8; j++) acc[i][j] = 0.0f;

    for (int k0 = 0; k0 < K; k0 += BK) {
        // load A tile (BM x BK), store transposed As[k][m]
#pragma unroll
        for (int l = 0; l < (BM * BK) / (NT * 4); ++l) {
            int idx = (tid + l * NT) * 4;          // in floats
            int r   = idx / BK;
            int kk  = idx % BK;                    // 0 or 4
            float4 v = make_float4(0.f, 0.f, 0.f, 0.f);
            if (row0 + r < N_NODES)
                v = *(const float4*)&A[(size_t)(row0 + r) * K + k0 + kk];
            if (A_GLOBAL) {                        // fused ReLU
                v.x = fmaxf(v.x, 0.f); v.y = fmaxf(v.y, 0.f);
                v.z = fmaxf(v.z, 0.f); v.w = fmaxf(v.w, 0.f);
            }
            As[kk + 0][r] = v.x; As[kk + 1][r] = v.y;
            As[kk + 2][r] = v.z; As[kk + 3][r] = v.w;
        }
        // load B tile (BK x BN)
#pragma unroll
        for (int l = 0; l < (BK * BN) / (NT * 4); ++l) {
            int idx = (tid + l * NT) * 4;
            int kk  = idx / BN;
            int n   = idx % BN;
            *(float4*)&Bs[kk][n] = *(const float4*)&B[(size_t)(k0 + kk) * BN + n];
        }
        __syncthreads();

#pragma unroll
        for (int kk = 0; kk < BK; ++kk) {
            float a[8], b[8];
            *(float4*)&a[0] = *(const float4*)&As[kk][ty * 8];
            *(float4*)&a[4] = *(const float4*)&As[kk][ty * 8 + 4];
            *(float4*)&b[0] = *(const float4*)&Bs[kk][tx * 8];
            *(float4*)&b[4] = *(const float4*)&Bs[kk][tx * 8 + 4];
#pragma unroll
            for (int i = 0; i < 8; i++)
#pragma unroll
                for (int j = 0; j < 8; j++)
                    acc[i][j] += a[i] * b[j];
        }
        __syncthreads();
    }

#pragma unroll
    for (int i = 0; i < 8; i++) {
        int r = row0 + ty * 8 + i;
        if (r < N_NODES) {
#pragma unroll
            for (int j = 0; j < 8; j += 4) {
                float4 v = make_float4(acc[i][j], acc[i][j + 1], acc[i][j + 2], acc[i][j + 3]);
                *(float4*)&C[(size_t)r * BN + tx * 8 + j] = v;
            }
        }
    }
}

// ---------------- self-loop init: out = tmp * dinv^2 + bias ----------------
// SRC_SEL: 1 -> g_tmp1, 2 -> g_tmp2.  OUT_PARAM: 0 -> g_h1, 1 -> outp.
template <int F, int SRC_SEL, int OUT_PARAM>
__global__ void k_selfinit(const float* __restrict__ bias, float* __restrict__ outp) {
    constexpr int F4 = F / 4;
    const float* tmp = (SRC_SEL == 1) ? (const float*)g_tmp1 : (const float*)g_tmp2;
    float* out = OUT_PARAM ? outp : (float*)g_h1;
    int idx = blockIdx.x * blockDim.x + threadIdx.x;   // float4 index
    if (idx >= N_NODES * F4) return;
    int i  = idx / F4;
    int f4 = idx % F4;
    float di = g_dinv[i];
    float s  = di * di;
    float4 v = ((const float4*)tmp)[idx];
    float4 b = ((const float4*)bias)[f4];
    v.x = v.x * s + b.x; v.y = v.y * s + b.y;
    v.z = v.z * s + b.z; v.w = v.w * s + b.w;
    ((float4*)out)[idx] = v;
}

// ---------------- edge scatter: out[d] += tmp[s] * dinv[s]*dinv[d] ----------------
// SRC_SEL: 1 -> g_tmp1, 2 -> g_tmp2.  OUT_PARAM: 0 -> g_h1, 1 -> outp.
template <int F, int SRC_SEL, int OUT_PARAM>
__global__ void k_scatter(const int* __restrict__ src, const int* __restrict__ dst,
                          float* __restrict__ outp) {
    constexpr int TPE = F / 4;     // threads per edge (32 or 16)
    const float* tmp = (SRC_SEL == 1) ? (const float*)g_tmp1 : (const float*)g_tmp2;
    float* out = OUT_PARAM ? outp : (float*)g_h1;
    long long gid = (long long)blockIdx.x * blockDim.x + threadIdx.x;
    int e    = (int)(gid / TPE);
    int lane = (int)(gid % TPE);
    if (e >= N_EDGES) return;
    int s = __ldg(&src[e]);
    int d = __ldg(&dst[e]);
    if ((unsigned)s >= N_NODES || (unsigned)d >= N_NODES) return;  // dtype insurance
    float norm = g_dinv[s] * g_dinv[d];
    float4 v = __ldg((const float4*)&tmp[(size_t)s * F + lane * 4]);
    float* p = &out[(size_t)d * F + lane * 4];
    atomicAdd(p + 0, v.x * norm);
    atomicAdd(p + 1, v.y * norm);
    atomicAdd(p + 2, v.z * norm);
    atomicAdd(p + 3, v.w * norm);
}

// ---------------- launch ----------------
extern "C" void kernel_launch(void* const* d_in, const int* in_sizes, int n_in,
                              void* d_out, int out_size) {
    const float* x   = (const float*)d_in[0];
    const int*   ei  = (const int*)d_in[1];       // edge_index materialized as int32
    const float* W1  = (const float*)d_in[2];
    const float* b1  = (const float*)d_in[3];
    const float* W2  = (const float*)d_in[4];
    const float* b2  = (const float*)d_in[5];
    float*       out = (float*)d_out;

    const int* src = ei;
    const int* dst = ei + N_EDGES;

    // degrees + norms (shared by both layers)
    k_init_deg <<<(N_NODES + 255) / 256, 256>>>();
    k_deg_edges<<<(N_EDGES + 255) / 256, 256>>>(dst);
    k_dinv     <<<(N_NODES + 255) / 256, 256>>>();

    // layer 1: tmp1 = x @ W1 ; h1 = A_norm * tmp1 + b1  (pre-ReLU)
    k_gemm<F1, 0, 1><<<(N_NODES + 127) / 128, 256>>>(x, W1);
    k_selfinit<F1, 1, 0><<<(N_NODES * (F1 / 4) + 255) / 256, 256>>>(b1, nullptr);
    {
        long long tot = (long long)N_EDGES * (F1 / 4);
        k_scatter<F1, 1, 0><<<(unsigned)((tot + 255) / 256), 256>>>(src, dst, nullptr);
    }

    // layer 2: tmp2 = relu(h1) @ W2 ; out = A_norm * tmp2 + b2
    k_gemm<F2, 1, 2><<<(N_NODES + 127) / 128, 128>>>(nullptr, W2);
    k_selfinit<F2, 2, 1><<<(N_NODES * (F2 / 4) + 255) / 256, 256>>>(b2, out);
    {
        long long tot = (long long)N_EDGES * (F2 / 4);
        k_scatter<F2, 2, 1><<<(unsigned)((tot + 255) / 256), 256>>>(src, dst, out);
    }
}

// round 4
// speedup vs baseline: 1.0966x; 1.0966x over previous
#include <cuda_runtime.h>
#include <math.h>

#define N_NODES 100000
#define N_EDGES 600000
#define F1 128
#define F2 64

// ---------------- scratch (static device globals; no allocation) ----------------
__device__ __align__(16) float g_dinv  [N_NODES];
__device__ int   g_count [N_NODES];          // in-degree (excl. self loop)
__device__ int   g_rowptr[N_NODES + 1];      // CSR row pointers (by dst)
__device__ int   g_cursor[N_NODES];          // fill cursors
__device__ int   g_esrc  [N_EDGES];          // src ids sorted by dst
__device__ __align__(16) float g_tmp1[N_NODES * F1];  // x @ W1
__device__ __align__(16) float g_h1  [N_NODES * F1];  // layer-1 out (pre-ReLU)
__device__ __align__(16) float g_tmp2[N_NODES * F2];  // relu(h1) @ W2

// ---------------- degree count ----------------
__global__ void k_zero_count() {
    int i = blockIdx.x * blockDim.x + threadIdx.x;
    if (i < N_NODES) g_count[i] = 0;
}

__global__ void k_count(const int* __restrict__ dst) {
    int e = blockIdx.x * blockDim.x + threadIdx.x;
    if (e < N_EDGES) {
        int d = dst[e];
        if ((unsigned)d < N_NODES) atomicAdd(&g_count[d], 1);
    }
}

__global__ void k_dinv() {
    int i = blockIdx.x * blockDim.x + threadIdx.x;
    if (i < N_NODES) g_dinv[i] = rsqrtf(1.0f + (float)g_count[i]);  // +1 self loop
}

// ---------------- single-block exclusive scan over g_count -> g_rowptr ----------
__global__ void k_scan() {     // launch with exactly 1024 threads, 1 block
    __shared__ int sh[1024];
    constexpr int CH = (N_NODES + 1023) / 1024;   // 98
    int t = threadIdx.x;
    int beg = t * CH;
    int end = min(beg + CH, N_NODES);
    int sum = 0;
    for (int i = beg; i < end; ++i) sum += g_count[i];
    sh[t] = sum;
    __syncthreads();
    // Hillis-Steele inclusive scan
    for (int off = 1; off < 1024; off <<= 1) {
        int v = (t >= off) ? sh[t - off] : 0;
        __syncthreads();
        sh[t] += v;
        __syncthreads();
    }
    int run = (t == 0) ? 0 : sh[t - 1];
    for (int i = beg; i < end; ++i) {
        g_rowptr[i] = run;
        g_cursor[i] = run;
        run += g_count[i];
    }
    if (t == 1023) g_rowptr[N_NODES] = run;
}

// ---------------- fill: scatter src ids into dst-sorted order ----------------
__global__ void k_fill(const int* __restrict__ src, const int* __restrict__ dst) {
    int e = blockIdx.x * blockDim.x + threadIdx.x;
    if (e >= N_EDGES) return;
    int s = src[e];
    int d = dst[e];
    if ((unsigned)s >= N_NODES || (unsigned)d >= N_NODES) return;
    int pos = atomicAdd(&g_cursor[d], 1);
    g_esrc[pos] = s;
}

// ---------------- SGEMM: C[M x BN] = op(A)[M x 128] * B[128 x BN] ----------------
// BM=128, BK=8, 8x8 thread tile.
// A_GLOBAL: 0 -> A param, 1 -> g_h1 (with ReLU on load)
// C_SEL:    1 -> g_tmp1, 2 -> g_tmp2
template <int BN, int A_GLOBAL, int C_SEL>
__global__ void __launch_bounds__(16 * (BN / 8))
k_gemm(const float* __restrict__ Ap, const float* __restrict__ B) {
    constexpr int BM = 128;
    constexpr int BK = 8;
    constexpr int K  = 128;
    constexpr int TX = BN / 8;
    constexpr int NT = 16 * TX;
    __shared__ float As[BK][BM];
    __shared__ float Bs[BK][BN];

    const float* A = A_GLOBAL ? (const float*)g_h1 : Ap;
    float* C = (C_SEL == 1) ? (float*)g_tmp1 : (float*)g_tmp2;

    const int tid = threadIdx.x;
    const int tx  = tid % TX;
    const int ty  = tid / TX;
    const int row0 = blockIdx.x * BM;

    float acc[8][8];
#pragma unroll
    for (int i = 0; i < 8; i++)
#pragma unroll
        for (int j = 0; j < 8; j++) acc[i][j] = 0.0f;

    for (int k0 = 0; k0 < K; k0 += BK) {
#pragma unroll
        for (int l = 0; l < (BM * BK) / (NT * 4); ++l) {
            int idx = (tid + l * NT) * 4;
            int r   = idx / BK;
            int kk  = idx % BK;
            float4 v = make_float4(0.f, 0.f, 0.f, 0.f);
            if (row0 + r < N_NODES)
                v = *(const float4*)&A[(size_t)(row0 + r) * K + k0 + kk];
            if (A_GLOBAL) {
                v.x = fmaxf(v.x, 0.f); v.y = fmaxf(v.y, 0.f);
                v.z = fmaxf(v.z, 0.f); v.w = fmaxf(v.w, 0.f);
            }
            As[kk + 0][r] = v.x; As[kk + 1][r] = v.y;
            As[kk + 2][r] = v.z; As[kk + 3][r] = v.w;
        }
#pragma unroll
        for (int l = 0; l < (BK * BN) / (NT * 4); ++l) {
            int idx = (tid + l * NT) * 4;
            int kk  = idx / BN;
            int n   = idx % BN;
            *(float4*)&Bs[kk][n] = *(const float4*)&B[(size_t)(k0 + kk) * BN + n];
        }
        __syncthreads();

#pragma unroll
        for (int kk = 0; kk < BK; ++kk) {
            float a[8], b[8];
            *(float4*)&a[0] = *(const float4*)&As[kk][ty * 8];
            *(float4*)&a[4] = *(const float4*)&As[kk][ty * 8 + 4];
            *(float4*)&b[0] = *(const float4*)&Bs[kk][tx * 8];
            *(float4*)&b[4] = *(const float4*)&Bs[kk][tx * 8 + 4];
#pragma unroll
            for (int i = 0; i < 8; i++)
#pragma unroll
                for (int j = 0; j < 8; j++)
                    acc[i][j] += a[i] * b[j];
        }
        __syncthreads();
    }

#pragma unroll
    for (int i = 0; i < 8; i++) {
        int r = row0 + ty * 8 + i;
        if (r < N_NODES) {
#pragma unroll
            for (int j = 0; j < 8; j += 4) {
                float4 v = make_float4(acc[i][j], acc[i][j + 1], acc[i][j + 2], acc[i][j + 3]);
                *(float4*)&C[(size_t)r * BN + tx * 8 + j] = v;
            }
        }
    }
}

// ---------------- gather aggregation ----------------
// out[i] = dinv[i] * ( sum_{s in N(i)} dinv[s]*tmp[s] + dinv[i]*tmp[i] ) + bias
// SRC_SEL: 1 -> g_tmp1, 2 -> g_tmp2.  OUT_PARAM: 0 -> g_h1, 1 -> outp.
template <int F, int SRC_SEL, int OUT_PARAM>
__global__ void k_gather(const float* __restrict__ bias, float* __restrict__ outp) {
    constexpr int TPR = F / 4;    // lanes per node (32 or 16)
    const float4* t4 = (SRC_SEL == 1) ? (const float4*)g_tmp1 : (const float4*)g_tmp2;
    float4* out = OUT_PARAM ? (float4*)outp : (float4*)g_h1;

    long long gid = (long long)blockIdx.x * blockDim.x + threadIdx.x;
    int node = (int)(gid / TPR);
    int lane = (int)(gid % TPR);
    if (node >= N_NODES) return;

    int beg = __ldg(&g_rowptr[node]);
    int end = __ldg(&g_rowptr[node + 1]);
    float di = g_dinv[node];

    float4 v = __ldg(&t4[(size_t)node * TPR + lane]);   // self term
    float4 acc;
    acc.x = di * v.x; acc.y = di * v.y; acc.z = di * v.z; acc.w = di * v.w;

    for (int j = beg; j < end; ++j) {
        int s = __ldg(&g_esrc[j]);
        float w = __ldg(&g_dinv[s]);
        float4 m = __ldg(&t4[(size_t)s * TPR + lane]);
        acc.x += w * m.x; acc.y += w * m.y; acc.z += w * m.z; acc.w += w * m.w;
    }

    float4 b = __ldg(&((const float4*)bias)[lane]);
    float4 r;
    r.x = di * acc.x + b.x; r.y = di * acc.y + b.y;
    r.z = di * acc.z + b.z; r.w = di * acc.w + b.w;
    out[(size_t)node * TPR + lane] = r;
}

// ---------------- launch ----------------
extern "C" void kernel_launch(void* const* d_in, const int* in_sizes, int n_in,
                              void* d_out, int out_size) {
    const float* x   = (const float*)d_in[0];
    const int*   ei  = (const int*)d_in[1];
    const float* W1  = (const float*)d_in[2];
    const float* b1  = (const float*)d_in[3];
    const float* W2  = (const float*)d_in[4];
    const float* b2  = (const float*)d_in[5];
    float*       out = (float*)d_out;

    const int* src = ei;
    const int* dst = ei + N_EDGES;

    // ---- build CSR (by dst) + dinv, shared by both layers ----
    k_zero_count<<<(N_NODES + 255) / 256, 256>>>();
    k_count     <<<(N_EDGES + 255) / 256, 256>>>(dst);
    k_dinv      <<<(N_NODES + 255) / 256, 256>>>();
    k_scan      <<<1, 1024>>>();
    k_fill      <<<(N_EDGES + 255) / 256, 256>>>(src, dst);

    // ---- layer 1: tmp1 = x @ W1 ; h1 = A_norm tmp1 + b1 ----
    k_gemm<F1, 0, 1><<<(N_NODES + 127) / 128, 256>>>(x, W1);
    {
        long long tot = (long long)N_NODES * (F1 / 4);
        k_gather<F1, 1, 0><<<(unsigned)((tot + 255) / 256), 256>>>(b1, nullptr);
    }

    // ---- layer 2: tmp2 = relu(h1) @ W2 ; out = A_norm tmp2 + b2 ----
    k_gemm<F2, 1, 2><<<(N_NODES + 127) / 128, 128>>>(nullptr, W2);
    {
        long long tot = (long long)N_NODES * (F2 / 4);
        k_gather<F2, 2, 1><<<(unsigned)((tot + 255) / 256), 256>>>(b2, out);
    }
}

// round 5
// speedup vs baseline: 1.7690x; 1.6131x over previous
#include <cuda_runtime.h>
#include <math.h>

#define N_NODES 100000
#define N_EDGES 600000
#define F1 128
#define F2 64

#define SCAN_BLK 1024
#define N_SCAN_BLOCKS ((N_NODES + SCAN_BLK - 1) / SCAN_BLK)   // 98

// ---------------- scratch (static device globals; no allocation) ----------------
__device__ __align__(16) float g_dinv  [N_NODES];
__device__ int   g_count   [N_NODES];          // in-degree (excl. self loop)
__device__ int   g_rowptr  [N_NODES + 1];      // CSR row pointers (by dst)
__device__ int   g_cursor  [N_NODES];          // fill cursors
__device__ int   g_esrc    [N_EDGES];          // src ids sorted by dst
__device__ int   g_blocksum[N_SCAN_BLOCKS];    // per-block totals
__device__ int   g_blockoff[N_SCAN_BLOCKS];    // exclusive offsets of block totals
__device__ __align__(16) float g_tmp1[N_NODES * F1];  // x @ W1
__device__ __align__(16) float g_h1  [N_NODES * F1];  // layer-1 out (pre-ReLU)
__device__ __align__(16) float g_tmp2[N_NODES * F2];  // relu(h1) @ W2

// ---------------- degree count ----------------
__global__ void k_zero_count() {
    int i = blockIdx.x * blockDim.x + threadIdx.x;
    if (i < N_NODES) g_count[i] = 0;
}

__global__ void k_count(const int* __restrict__ dst) {
    int e = blockIdx.x * blockDim.x + threadIdx.x;
    if (e < N_EDGES) {
        int d = dst[e];
        if ((unsigned)d < N_NODES) atomicAdd(&g_count[d], 1);
    }
}

__global__ void k_dinv() {
    int i = blockIdx.x * blockDim.x + threadIdx.x;
    if (i < N_NODES) g_dinv[i] = rsqrtf(1.0f + (float)g_count[i]);  // +1 self loop
}

// ---------------- parallel scan, phase 1: per-block exclusive scan ----------------
__global__ void __launch_bounds__(SCAN_BLK)
k_scan_block() {
    __shared__ int warp_sums[32];
    int t   = threadIdx.x;
    int gi  = blockIdx.x * SCAN_BLK + t;
    int val = (gi < N_NODES) ? g_count[gi] : 0;

    int lane = t & 31, wid = t >> 5;
    // warp-inclusive scan
    int inc = val;
#pragma unroll
    for (int off = 1; off < 32; off <<= 1) {
        int v = __shfl_up_sync(0xffffffffu, inc, off);
        if (lane >= off) inc += v;
    }
    if (lane == 31) warp_sums[wid] = inc;
    __syncthreads();
    if (wid == 0) {
        int ws = (lane < SCAN_BLK / 32) ? warp_sums[lane] : 0;
        int wi = ws;
#pragma unroll
        for (int off = 1; off < 32; off <<= 1) {
            int v = __shfl_up_sync(0xffffffffu, wi, off);
            if (lane >= off) wi += v;
        }
        warp_sums[lane] = wi - ws;   // exclusive warp offset
        if (lane == SCAN_BLK / 32 - 1 && wi > 0) g_blocksum[blockIdx.x] = wi;
        else if (lane == SCAN_BLK / 32 - 1) g_blocksum[blockIdx.x] = wi;
    }
    __syncthreads();
    int excl = inc - val + warp_sums[wid];
    if (gi < N_NODES) g_rowptr[gi] = excl;     // pre-offset local prescan
}

// ---------------- phase 2: scan the 98 block totals (1 tiny block) ----------------
__global__ void k_scan_tops() {
    __shared__ int sh[128];
    int t = threadIdx.x;
    int v = (t < N_SCAN_BLOCKS) ? g_blocksum[t] : 0;
    sh[t] = v;
    __syncthreads();
    for (int off = 1; off < 128; off <<= 1) {
        int u = (t >= off) ? sh[t - off] : 0;
        __syncthreads();
        sh[t] += u;
        __syncthreads();
    }
    if (t < N_SCAN_BLOCKS) g_blockoff[t] = sh[t] - v;   // exclusive
    if (t == 127) g_rowptr[N_NODES] = sh[127];          // total edge count kept
}

// ---------------- phase 3: add block offsets, init cursors ----------------
__global__ void __launch_bounds__(SCAN_BLK)
k_scan_add() {
    int gi = blockIdx.x * SCAN_BLK + threadIdx.x;
    if (gi < N_NODES) {
        int r = g_rowptr[gi] + g_blockoff[blockIdx.x];
        g_rowptr[gi] = r;
        g_cursor[gi] = r;
    }
}

// ---------------- fill: scatter src ids into dst-sorted order ----------------
__global__ void k_fill(const int* __restrict__ src, const int* __restrict__ dst) {
    int e = blockIdx.x * blockDim.x + threadIdx.x;
    if (e >= N_EDGES) return;
    int s = src[e];
    int d = dst[e];
    if ((unsigned)s >= N_NODES || (unsigned)d >= N_NODES) return;
    int pos = atomicAdd(&g_cursor[d], 1);
    g_esrc[pos] = s;
}

// ---------------- SGEMM: C[M x BN] = op(A)[M x 128] * B[128 x BN] ----------------
// BM=128, BK=8, 8x8 thread tile.
// A_GLOBAL: 0 -> A param, 1 -> g_h1 (with ReLU on load)
// C_SEL:    1 -> g_tmp1, 2 -> g_tmp2
template <int BN, int A_GLOBAL, int C_SEL>
__global__ void __launch_bounds__(16 * (BN / 8))
k_gemm(const float* __restrict__ Ap, const float* __restrict__ B) {
    constexpr int BM = 128;
    constexpr int BK = 8;
    constexpr int K  = 128;
    constexpr int TX = BN / 8;
    constexpr int NT = 16 * TX;
    __shared__ float As[BK][BM];
    __shared__ float Bs[BK][BN];

    const float* A = A_GLOBAL ? (const float*)g_h1 : Ap;
    float* C = (C_SEL == 1) ? (float*)g_tmp1 : (float*)g_tmp2;

    const int tid = threadIdx.x;
    const int tx  = tid % TX;
    const int ty  = tid / TX;
    const int row0 = blockIdx.x * BM;

    float acc[8][8];
#pragma unroll
    for (int i = 0; i < 8; i++)
#pragma unroll
        for (int j = 0; j < 8; j++) acc[i][j] = 0.0f;

    for (int k0 = 0; k0 < K; k0 += BK) {
#pragma unroll
        for (int l = 0; l < (BM * BK) / (NT * 4); ++l) {
            int idx = (tid + l * NT) * 4;
            int r   = idx / BK;
            int kk  = idx % BK;
            float4 v = make_float4(0.f, 0.f, 0.f, 0.f);
            if (row0 + r < N_NODES)
                v = *(const float4*)&A[(size_t)(row0 + r) * K + k0 + kk];
            if (A_GLOBAL) {
                v.x = fmaxf(v.x, 0.f); v.y = fmaxf(v.y, 0.f);
                v.z = fmaxf(v.z, 0.f); v.w = fmaxf(v.w, 0.f);
            }
            As[kk + 0][r] = v.x; As[kk + 1][r] = v.y;
            As[kk + 2][r] = v.z; As[kk + 3][r] = v.w;
        }
#pragma unroll
        for (int l = 0; l < (BK * BN) / (NT * 4); ++l) {
            int idx = (tid + l * NT) * 4;
            int kk  = idx / BN;
            int n   = idx % BN;
            *(float4*)&Bs[kk][n] = *(const float4*)&B[(size_t)(k0 + kk) * BN + n];
        }
        __syncthreads();

#pragma unroll
        for (int kk = 0; kk < BK; ++kk) {
            float a[8], b[8];
            *(float4*)&a[0] = *(const float4*)&As[kk][ty * 8];
            *(float4*)&a[4] = *(const float4*)&As[kk][ty * 8 + 4];
            *(float4*)&b[0] = *(const float4*)&Bs[kk][tx * 8];
            *(float4*)&b[4] = *(const float4*)&Bs[kk][tx * 8 + 4];
#pragma unroll
            for (int i = 0; i < 8; i++)
#pragma unroll
                for (int j = 0; j < 8; j++)
                    acc[i][j] += a[i] * b[j];
        }
        __syncthreads();
    }

#pragma unroll
    for (int i = 0; i < 8; i++) {
        int r = row0 + ty * 8 + i;
        if (r < N_NODES) {
#pragma unroll
            for (int j = 0; j < 8; j += 4) {
                float4 v = make_float4(acc[i][j], acc[i][j + 1], acc[i][j + 2], acc[i][j + 3]);
                *(float4*)&C[(size_t)r * BN + tx * 8 + j] = v;
            }
        }
    }
}

// ---------------- gather aggregation ----------------
// out[i] = dinv[i] * ( sum_{s in N(i)} dinv[s]*tmp[s] + dinv[i]*tmp[i] ) + bias
// SRC_SEL: 1 -> g_tmp1, 2 -> g_tmp2.  OUT_PARAM: 0 -> g_h1, 1 -> outp.
template <int F, int SRC_SEL, int OUT_PARAM>
__global__ void k_gather(const float* __restrict__ bias, float* __restrict__ outp) {
    constexpr int TPR = F / 4;    // lanes per node (32 or 16)
    const float4* t4 = (SRC_SEL == 1) ? (const float4*)g_tmp1 : (const float4*)g_tmp2;
    float4* out = OUT_PARAM ? (float4*)outp : (float4*)g_h1;

    long long gid = (long long)blockIdx.x * blockDim.x + threadIdx.x;
    int node = (int)(gid / TPR);
    int lane = (int)(gid % TPR);
    if (node >= N_NODES) return;

    int beg = __ldg(&g_rowptr[node]);
    int end = __ldg(&g_rowptr[node + 1]);
    float di = g_dinv[node];

    float4 v = __ldg(&t4[(size_t)node * TPR + lane]);   // self term
    float4 acc;
    acc.x = di * v.x; acc.y = di * v.y; acc.z = di * v.z; acc.w = di * v.w;

    for (int j = beg; j < end; ++j) {
        int s = __ldg(&g_esrc[j]);
        float w = __ldg(&g_dinv[s]);
        float4 m = __ldg(&t4[(size_t)s * TPR + lane]);
        acc.x += w * m.x; acc.y += w * m.y; acc.z += w * m.z; acc.w += w * m.w;
    }

    float4 b = __ldg(&((const float4*)bias)[lane]);
    float4 r;
    r.x = di * acc.x + b.x; r.y = di * acc.y + b.y;
    r.z = di * acc.z + b.z; r.w = di * acc.w + b.w;
    out[(size_t)node * TPR + lane] = r;
}

// ---------------- launch ----------------
extern "C" void kernel_launch(void* const* d_in, const int* in_sizes, int n_in,
                              void* d_out, int out_size) {
    const float* x   = (const float*)d_in[0];
    const int*   ei  = (const int*)d_in[1];
    const float* W1  = (const float*)d_in[2];
    const float* b1  = (const float*)d_in[3];
    const float* W2  = (const float*)d_in[4];
    const float* b2  = (const float*)d_in[5];
    float*       out = (float*)d_out;

    const int* src = ei;
    const int* dst = ei + N_EDGES;

    // ---- build CSR (by dst) + dinv, shared by both layers ----
    k_zero_count<<<(N_NODES + 255) / 256, 256>>>();
    k_count     <<<(N_EDGES + 255) / 256, 256>>>(dst);
    k_dinv      <<<(N_NODES + 255) / 256, 256>>>();
    k_scan_block<<<N_SCAN_BLOCKS, SCAN_BLK>>>();
    k_scan_tops <<<1, 128>>>();
    k_scan_add  <<<N_SCAN_BLOCKS, SCAN_BLK>>>();
    k_fill      <<<(N_EDGES + 255) / 256, 256>>>(src, dst);

    // ---- layer 1: tmp1 = x @ W1 ; h1 = A_norm tmp1 + b1 ----
    k_gemm<F1, 0, 1><<<(N_NODES + 127) / 128, 256>>>(x, W1);
    {
        long long tot = (long long)N_NODES * (F1 / 4);
        k_gather<F1, 1, 0><<<(unsigned)((tot + 255) / 256), 256>>>(b1, nullptr);
    }

    // ---- layer 2: tmp2 = relu(h1) @ W2 ; out = A_norm tmp2 + b2 ----
    k_gemm<F2, 1, 2><<<(N_NODES + 127) / 128, 128>>>(nullptr, W2);
    {
        long long tot = (long long)N_NODES * (F2 / 4);
        k_gather<F2, 2, 1><<<(unsigned)((tot + 255) / 256), 256>>>(b2, out);
    }
}